// round 15
// baseline (speedup 1.0000x reference)
#include <cuda_runtime.h>

// Shape fixed by dataset: disp [4,1,1024,1280] f32, kernel_raw [4,8,1024,1280] f32
#define BB    4
#define HH    1024
#define WW    1280
#define PLANE (HH * WW)
#define NPIX  (BB * PLANE)     // 5242880

#define TT    8                // fused iterations per pass (24 = 3 passes)
#define TS    48               // output tile (quad-aligned: halo 8 = 2 quads)
#define RS    64               // region tile
#define NTX   ((WW + TS - 1) / TS)   // 27
#define NTY   ((HH + TS - 1) / TS)   // 22
#define SROW  64               // floats per smem row
#define FULLMASK 0xFFFFFFFFu

__device__ float g_w[(size_t)8 * NPIX];   // normalized fp32 weights, planar [8][B*H*W]
__device__ float g_ping[NPIX];            // scratch disparity buffers
__device__ float g_pong[NPIX];

// ---- packed f32x2 helpers (SASS FFMA2/FMUL2; per-lane IEEE rn == scalar) ----
static __device__ __forceinline__ unsigned long long u64of(float2 v) {
    return reinterpret_cast<unsigned long long&>(v);
}
static __device__ __forceinline__ float2 f2of(unsigned long long v) {
    return reinterpret_cast<float2&>(v);
}
static __device__ __forceinline__ float2 fma2(float2 a, float2 b, float2 c) {
    unsigned long long r;
    asm("fma.rn.f32x2 %0, %1, %2, %3;"
        : "=l"(r) : "l"(u64of(a)), "l"(u64of(b)), "l"(u64of(c)));
    return f2of(r);
}
static __device__ __forceinline__ float2 mul2(float2 a, float2 b) {
    unsigned long long r;
    asm("mul.rn.f32x2 %0, %1, %2;" : "=l"(r) : "l"(u64of(a)), "l"(u64of(b)));
    return f2of(r);
}

// ---------------------------------------------------------------------------
// Fused pass: 8 stencil iterations, trapezoidal blocking (64x64 region ->
// 48x48 output). 1024 threads/CTA, 4 px/thread; px pairs processed with
// packed f32x2 FMAs (18 FFMA2 vs 36 FFMA per iteration).
// Lateral halos via warp shuffle; smem ops per iter: 2x LDS.128 + 1x STS.128.
// DIRECT form: d' = w0*d + sum_i w_i*d_i, w0 = 1 - sum w (round-2 numerics,
// bitwise identical per lane). Out-of-image px: w==0 -> stays 0 (zero pad).
// PREP: pass 1 normalizes kernel_raw in-register, stores g_w owned window.
// ---------------------------------------------------------------------------
template <bool PREP, bool CLIP>
__global__ void __launch_bounds__(1024) fused_kernel(const float* __restrict__ din,
                                                     float* __restrict__ dout,
                                                     const float* __restrict__ raw) {
    __shared__ float sbuf[2][RS * SROW];

    const int tid = threadIdx.x;
    const int q   = tid & 15;           // quad
    const int r   = tid >> 4;           // region row 0..63
    const int x0  = q << 2;             // region col of px0

    const int b   = blockIdx.z;
    const int gy  = blockIdx.y * TS - TT + r;
    const int gx0 = blockIdx.x * TS - TT + x0;
    const bool rowIn = (gy >= 0) && (gy < HH);
    const size_t rowOff = (size_t)(b * HH + gy) * WW;  // deref'd only when rowIn
    const bool pxIn  = rowIn && gx0 >= 0 && gx0 < WW;

    // ---- own disparity quad (zero outside image) ----
    float2 M0, M1;                      // (d0,d1), (d2,d3)
    {
        float4 v = make_float4(0.f, 0.f, 0.f, 0.f);
        if (pxIn) v = *reinterpret_cast<const float4*>(din + rowOff + gx0);
        M0 = make_float2(v.x, v.y); M1 = make_float2(v.z, v.w);
    }

    // ---- per-pixel weights into registers (zero outside image) ----
    float w[8][4];                       // [channel][px]
#pragma unroll
    for (int ch = 0; ch < 8; ch++) {
        const float* base = PREP
            ? raw + (size_t)(b * 8 + ch) * PLANE
            : g_w + (size_t)ch * NPIX + (size_t)b * PLANE;
        float4 v = make_float4(0.f, 0.f, 0.f, 0.f);
        if (pxIn) v = *reinterpret_cast<const float4*>(base + (size_t)gy * WW + gx0);
        w[ch][0] = v.x; w[ch][1] = v.y; w[ch][2] = v.z; w[ch][3] = v.w;
    }

    if (PREP) {
#pragma unroll
        for (int p = 0; p < 4; p++) {
            float s = 0.f;
#pragma unroll
            for (int ch = 0; ch < 8; ch++) s += fabsf(w[ch][p]);
            float inv = __frcp_rn(s + 1e-9f);
#pragma unroll
            for (int ch = 0; ch < 8; ch++) w[ch][p] *= inv;
        }
        // store owned (non-overlapping) window: region cols [8,56), rows [8,56)
        if (q >= 2 && q <= 13 && r >= TT && r < RS - TT && gy < HH && gx0 < WW) {
#pragma unroll
            for (int ch = 0; ch < 8; ch++)
                *reinterpret_cast<float4*>(g_w + (size_t)ch * NPIX + rowOff + gx0) =
                    make_float4(w[ch][0], w[ch][1], w[ch][2], w[ch][3]);
        }
    }

    // center weight w0 = 1 - sum(w), then pack all weights as px-pairs
    float2 W[8][2], W0[2];
#pragma unroll
    for (int p = 0; p < 4; p++) {
        float s = ((w[0][p] + w[1][p]) + (w[2][p] + w[3][p])) +
                  ((w[4][p] + w[5][p]) + (w[6][p] + w[7][p]));
        float w0s = 1.0f - s;
        if (p < 2) { reinterpret_cast<float*>(&W0[0])[p] = w0s; }
        else       { reinterpret_cast<float*>(&W0[1])[p - 2] = w0s; }
    }
#pragma unroll
    for (int ch = 0; ch < 8; ch++) {
        W[ch][0] = make_float2(w[ch][0], w[ch][1]);
        W[ch][1] = make_float2(w[ch][2], w[ch][3]);
    }

    // ---- initial publish to buffer 0 ----
    *reinterpret_cast<float4*>(&sbuf[0][r * SROW + x0]) =
        make_float4(M0.x, M0.y, M1.x, M1.y);
    __syncthreads();

    const bool act = (r >= 1) && (r <= RS - 2);
    // precomputed offsets (clamped rows: result unused when inactive)
    const int trOff = ((r >= 1) ? r - 1 : 0) * SROW + x0;
    const int brOff = ((r <= RS - 2) ? r + 1 : RS - 1) * SROW + x0;
    const int mrOff = r * SROW + x0;

    // ---- 8 fused iterations ----
#pragma unroll
    for (int it = 0; it < TT; it++) {
        const float* cur = sbuf[it & 1];

        // own-row lateral halos via shuffle (start-of-iter state)
        float hl = __shfl_up_sync(FULLMASK, M1.y, 1);
        float hr = __shfl_down_sync(FULLMASK, M0.x, 1);

        // m-row operand pairs
        float2 mL  = make_float2(hl, M0.x);     // (d-1, d0)
        float2 mC  = make_float2(M0.y, M1.x);   // (d1, d2)
        float2 mR  = make_float2(M1.y, hr);     // (d3, d+4)

        float2 A0, A1;
        // centers
        A0 = mul2(W0[0], M0);
        A1 = mul2(W0[1], M1);
        // m-row taps: ch3 = (y,x+1), ch7 = (y,x-1)
        A0 = fma2(W[3][0], mC, A0);
        A1 = fma2(W[3][1], mR, A1);
        A0 = fma2(W[7][0], mL, A0);
        A1 = fma2(W[7][1], mC, A1);

        // top row: wide load + shuffled halos
        {
            float4 a = *reinterpret_cast<const float4*>(cur + trOff);
            float tl = __shfl_up_sync(FULLMASK, a.w, 1);
            float tr = __shfl_down_sync(FULLMASK, a.x, 1);
            float2 Ta = make_float2(a.x, a.y), Tb = make_float2(a.z, a.w);
            float2 tL = make_float2(tl, a.x);
            float2 tC = make_float2(a.y, a.z);
            float2 tR = make_float2(a.w, tr);
            A0 = fma2(W[0][0], tL, A0);  // (y-1, x-1)
            A1 = fma2(W[0][1], tC, A1);
            A0 = fma2(W[1][0], Ta, A0);  // (y-1, x  )
            A1 = fma2(W[1][1], Tb, A1);
            A0 = fma2(W[2][0], tC, A0);  // (y-1, x+1)
            A1 = fma2(W[2][1], tR, A1);
        }

        // bottom row: wide load + shuffled halos
        {
            float4 a = *reinterpret_cast<const float4*>(cur + brOff);
            float bl = __shfl_up_sync(FULLMASK, a.w, 1);
            float br = __shfl_down_sync(FULLMASK, a.x, 1);
            float2 Ba = make_float2(a.x, a.y), Bb = make_float2(a.z, a.w);
            float2 bL = make_float2(bl, a.x);
            float2 bC = make_float2(a.y, a.z);
            float2 bR = make_float2(a.w, br);
            A0 = fma2(W[4][0], bC, A0);  // (y+1, x+1)
            A1 = fma2(W[4][1], bR, A1);
            A0 = fma2(W[5][0], Ba, A0);  // (y+1, x  )
            A1 = fma2(W[5][1], Bb, A1);
            A0 = fma2(W[6][0], bL, A0);  // (y+1, x-1)
            A1 = fma2(W[6][1], bC, A1);
        }

        // region-edge columns keep old value (consumed only while still valid;
        // also absorbs garbage shuffles at halfwarp boundaries)
        if (q == 0)  A0.x = M0.x;
        if (q == 15) A1.y = M1.y;

        if (act) { M0 = A0; M1 = A1; }

        if (it < TT - 1) {
            *reinterpret_cast<float4*>(&sbuf[(it + 1) & 1][mrOff]) =
                make_float4(M0.x, M0.y, M1.x, M1.y);
            __syncthreads();
        }
    }

    // ---- epilogue: write owned window (region cols [8,56), rows [8,56)) ----
    if (q >= 2 && q <= 13 && r >= TT && r < RS - TT && gy < HH && gx0 < WW) {
        float4 o = make_float4(M0.x, M0.y, M1.x, M1.y);
        if (CLIP) {
            o.x = fminf(fmaxf(o.x, 0.f), 256.f);
            o.y = fminf(fmaxf(o.y, 0.f), 256.f);
            o.z = fminf(fmaxf(o.z, 0.f), 256.f);
            o.w = fminf(fmaxf(o.w, 0.f), 256.f);
        }
        *reinterpret_cast<float4*>(dout + rowOff + gx0) = o;
    }
}

// ---------------------------------------------------------------------------
extern "C" void kernel_launch(void* const* d_in, const int* in_sizes, int n_in,
                              void* d_out, int out_size) {
    const float* disp = (const float*)d_in[0];
    const float* raw  = (const float*)d_in[1];
    if (n_in >= 2 && in_sizes[0] > in_sizes[1]) {  // defensive order check
        const float* t = disp; disp = raw; raw = t;
    }
    float* out = (float*)d_out;

    float* ping = nullptr; float* pong = nullptr;
    cudaGetSymbolAddress((void**)&ping, g_ping);   // address queries; capture-safe
    cudaGetSymbolAddress((void**)&pong, g_pong);

    dim3 grid(NTX, NTY, BB);
    // 3 fused passes x 8 iterations = 24; pass 1 also normalizes weights
    fused_kernel<true,  false><<<grid, 1024>>>(disp, ping, raw);
    fused_kernel<false, false><<<grid, 1024>>>(ping, pong, raw);
    fused_kernel<false, true ><<<grid, 1024>>>(pong, out,  raw);
}

// round 17
// speedup vs baseline: 1.0064x; 1.0064x over previous
#include <cuda_runtime.h>

// Shape fixed by dataset: disp [4,1,1024,1280] f32, kernel_raw [4,8,1024,1280] f32
#define BB    4
#define HH    1024
#define WW    1280
#define PLANE (HH * WW)
#define NPIX  (BB * PLANE)     // 5242880

#define TT    8                // fused iterations per pass (24 = 3 passes)
#define TS    48               // output tile (quad-aligned: halo 8 = 2 quads)
#define RS    64               // region tile
#define NTX   ((WW + TS - 1) / TS)   // 27
#define NTY   ((HH + TS - 1) / TS)   // 22
#define SROW  64               // floats per smem row
#define FULLMASK 0xFFFFFFFFu

__device__ float g_ping[NPIX];            // scratch disparity buffers
__device__ float g_pong[NPIX];

// ---------------------------------------------------------------------------
// Fused pass: 8 stencil iterations, trapezoidal blocking (64x64 region ->
// 48x48 output). 1024 threads/CTA, 4 px/thread:
//   q = tid & 15 (quad), r = tid >> 4 (region row), lane = (r&1)*16 + q.
// EVERY pass loads kernel_raw and normalizes in registers (no weight
// write-back / re-read stream: normalization is ~21 instr once per pass,
// bitwise identical across passes since inputs + instruction sequence are
// identical). Lateral halos via warp shuffle; smem per iter: 2x LDS.128 +
// 1x STS.128. DIRECT form: d' = w0*d + sum_i w_i*d_i, w0 = 1 - sum w.
// Out-of-image px: w==0 -> w0=1 -> stays 0 (zero padding preserved).
// ---------------------------------------------------------------------------
template <bool CLIP>
__global__ void __launch_bounds__(1024) fused_kernel(const float* __restrict__ din,
                                                     float* __restrict__ dout,
                                                     const float* __restrict__ raw) {
    __shared__ float sbuf[2][RS * SROW];

    const int tid = threadIdx.x;
    const int q   = tid & 15;           // quad
    const int r   = tid >> 4;           // region row 0..63
    const int x0  = q << 2;             // region col of px0

    const int b   = blockIdx.z;
    const int gy  = blockIdx.y * TS - TT + r;
    const int gx0 = blockIdx.x * TS - TT + x0;
    const bool rowIn = (gy >= 0) && (gy < HH);
    const size_t rowOff = (size_t)(b * HH + gy) * WW;  // deref'd only when rowIn
    const bool pxIn  = rowIn && gx0 >= 0 && gx0 < WW;

    // ---- own disparity quad (zero outside image) ----
    float mm[6];                         // [halo-1, px0..3, halo+4]
    {
        float4 v = make_float4(0.f, 0.f, 0.f, 0.f);
        if (pxIn) v = *reinterpret_cast<const float4*>(din + rowOff + gx0);
        mm[1] = v.x; mm[2] = v.y; mm[3] = v.z; mm[4] = v.w;
    }

    // ---- raw weights into registers (zero outside image), normalize ----
    float w[8][4];                       // [channel][px]
#pragma unroll
    for (int ch = 0; ch < 8; ch++) {
        const float* base = raw + (size_t)(b * 8 + ch) * PLANE;
        float4 v = make_float4(0.f, 0.f, 0.f, 0.f);
        if (pxIn) v = *reinterpret_cast<const float4*>(base + (size_t)gy * WW + gx0);
        w[ch][0] = v.x; w[ch][1] = v.y; w[ch][2] = v.z; w[ch][3] = v.w;
    }
    float w0[4];
#pragma unroll
    for (int p = 0; p < 4; p++) {
        float s = 0.f;
#pragma unroll
        for (int ch = 0; ch < 8; ch++) s += fabsf(w[ch][p]);
        float inv = __frcp_rn(s + 1e-9f);
#pragma unroll
        for (int ch = 0; ch < 8; ch++) w[ch][p] *= inv;
        float t = ((w[0][p] + w[1][p]) + (w[2][p] + w[3][p])) +
                  ((w[4][p] + w[5][p]) + (w[6][p] + w[7][p]));
        w0[p] = 1.0f - t;
    }

    // ---- initial publish to buffer 0 ----
    *reinterpret_cast<float4*>(&sbuf[0][r * SROW + x0]) =
        make_float4(mm[1], mm[2], mm[3], mm[4]);
    __syncthreads();

    const bool act = (r >= 1) && (r <= RS - 2);
    // precomputed offsets (clamped rows: result unused when inactive)
    const int trOff = ((r >= 1) ? r - 1 : 0) * SROW + x0;
    const int brOff = ((r <= RS - 2) ? r + 1 : RS - 1) * SROW + x0;
    const int mrOff = r * SROW + x0;

    // ---- 8 fused iterations ----
#pragma unroll
    for (int it = 0; it < TT; it++) {
        const float* cur = sbuf[it & 1];

        // own-row lateral halos via shuffle (start-of-iter state)
        mm[0] = __shfl_up_sync(FULLMASK, mm[4], 1);
        mm[5] = __shfl_down_sync(FULLMASK, mm[1], 1);

        float t[6], acc[4];

        // top row: wide load + shuffled halos
        {
            float4 a = *reinterpret_cast<const float4*>(cur + trOff);
            t[1] = a.x; t[2] = a.y; t[3] = a.z; t[4] = a.w;
            t[0] = __shfl_up_sync(FULLMASK, a.w, 1);
            t[5] = __shfl_down_sync(FULLMASK, a.x, 1);
        }
#pragma unroll
        for (int p = 0; p < 4; p++) {
            float a = w0[p] * mm[p + 1];
            a = fmaf(w[0][p], t[p],      a);  // (y-1, x-1)
            a = fmaf(w[1][p], t[p + 1],  a);  // (y-1, x  )
            a = fmaf(w[2][p], t[p + 2],  a);  // (y-1, x+1)
            a = fmaf(w[3][p], mm[p + 2], a);  // (y  , x+1)
            a = fmaf(w[7][p], mm[p],     a);  // (y  , x-1)
            acc[p] = a;
        }

        // bottom row: wide load + shuffled halos (reuse t[])
        {
            float4 a = *reinterpret_cast<const float4*>(cur + brOff);
            t[1] = a.x; t[2] = a.y; t[3] = a.z; t[4] = a.w;
            t[0] = __shfl_up_sync(FULLMASK, a.w, 1);
            t[5] = __shfl_down_sync(FULLMASK, a.x, 1);
        }
#pragma unroll
        for (int p = 0; p < 4; p++) {
            acc[p] = fmaf(w[4][p], t[p + 2], acc[p]);  // (y+1, x+1)
            acc[p] = fmaf(w[5][p], t[p + 1], acc[p]);  // (y+1, x  )
            acc[p] = fmaf(w[6][p], t[p],     acc[p]);  // (y+1, x-1)
        }

        // region-edge columns keep old value (consumed only while still valid;
        // also absorbs garbage shuffles at halfwarp boundaries)
        if (q == 0)  acc[0] = mm[1];
        if (q == 15) acc[3] = mm[4];

        if (act) {
            mm[1] = acc[0]; mm[2] = acc[1]; mm[3] = acc[2]; mm[4] = acc[3];
        }

        if (it < TT - 1) {
            *reinterpret_cast<float4*>(&sbuf[(it + 1) & 1][mrOff]) =
                make_float4(mm[1], mm[2], mm[3], mm[4]);
            __syncthreads();
        }
    }

    // ---- epilogue: write owned window (region cols [8,56), rows [8,56)) ----
    if (q >= 2 && q <= 13 && r >= TT && r < RS - TT && gy < HH && gx0 < WW) {
        if (CLIP) {
#pragma unroll
            for (int p = 0; p < 4; p++)
                mm[1 + p] = fminf(fmaxf(mm[1 + p], 0.f), 256.f);
        }
        *reinterpret_cast<float4*>(dout + rowOff + gx0) =
            make_float4(mm[1], mm[2], mm[3], mm[4]);
    }
}

// ---------------------------------------------------------------------------
extern "C" void kernel_launch(void* const* d_in, const int* in_sizes, int n_in,
                              void* d_out, int out_size) {
    const float* disp = (const float*)d_in[0];
    const float* raw  = (const float*)d_in[1];
    if (n_in >= 2 && in_sizes[0] > in_sizes[1]) {  // defensive order check
        const float* t = disp; disp = raw; raw = t;
    }
    float* out = (float*)d_out;

    float* ping = nullptr; float* pong = nullptr;
    cudaGetSymbolAddress((void**)&ping, g_ping);   // address queries; capture-safe
    cudaGetSymbolAddress((void**)&pong, g_pong);

    dim3 grid(NTX, NTY, BB);
    // 3 fused passes x 8 iterations = 24; weights normalized in-register
    // in every pass (no weight write-back stream)
    fused_kernel<false><<<grid, 1024>>>(disp, ping, raw);
    fused_kernel<false><<<grid, 1024>>>(ping, pong, raw);
    fused_kernel<true ><<<grid, 1024>>>(pong, out,  raw);
}